// round 1
// baseline (speedup 1.0000x reference)
#include <cuda_runtime.h>
#include <math.h>

#define DD 128
#define MAXN 100000
#define MAXND (MAXN * DD)

// Scratch (static device globals; allocation is forbidden)
__device__ float g_h[MAXND];      // GEMM output of current layer
__device__ float g_agg[MAXND];    // aggregation output (input to next layer)
__device__ float g_deg[MAXN];
__device__ float g_dinv[MAXN];
__device__ float g_colsum[DD];
__device__ float g_sumsq[1];
__device__ float g_mu[DD];
__device__ float g_inv[1];

// ---------------------------------------------------------------------------
__global__ void k_deg_init(float* deg, int N) {
    int i = blockIdx.x * blockDim.x + threadIdx.x;
    if (i < N) deg[i] = 1.0f;  // self-loop
}

__global__ void k_deg_count(const int* __restrict__ dst, float* deg, int E) {
    int e = blockIdx.x * blockDim.x + threadIdx.x;
    if (e < E) atomicAdd(&deg[dst[e]], 1.0f);
}

__global__ void k_dinv(const float* __restrict__ deg, float* dinv, int N) {
    int i = blockIdx.x * blockDim.x + threadIdx.x;
    if (i < N) dinv[i] = 1.0f / sqrtf(deg[i]);
}

// ---------------------------------------------------------------------------
// GEMM: H[N,128] = f(X)[N,128] @ W[128,128]
// f = identity (applyNorm=0) or PairNorm+ReLU using (mu, inv) from prev layer.
// Tile: 64 rows x 128 cols per block, 256 threads, K chunked by 32.
__global__ void k_gemm(const float* __restrict__ X, const float* __restrict__ W,
                       float* __restrict__ H, const float* __restrict__ mu,
                       const float* __restrict__ invp, int applyNorm, int N) {
    __shared__ float ws[32][DD];
    __shared__ float xs[32][65];   // transposed x tile, pad 65 -> conflict-free
    const int tid = threadIdx.x;
    const int row0 = blockIdx.x * 64;
    const float inv = applyNorm ? invp[0] : 0.0f;

    float acc[4][8];
#pragma unroll
    for (int i = 0; i < 4; i++)
#pragma unroll
        for (int j = 0; j < 8; j++) acc[i][j] = 0.0f;

    const int tr = tid >> 4;   // 0..15 -> rows tr*4 .. tr*4+3
    const int tc = tid & 15;   // cols tc + 16*j

    for (int k0 = 0; k0 < DD; k0 += 32) {
        // stage W chunk [32 x 128], coalesced
        for (int i = tid; i < 32 * DD; i += 256) {
            ws[i >> 7][i & 127] = W[((k0 + (i >> 7)) << 7) + (i & 127)];
        }
        // stage X chunk transposed [32k x 64rows], fused PairNorm+ReLU
        for (int i = tid; i < 64 * 32; i += 256) {
            int r = i >> 5, k = i & 31;
            int gr = row0 + r;
            float v = 0.0f;
            if (gr < N) {
                v = X[((size_t)gr << 7) + k0 + k];
                if (applyNorm) v = fmaxf((v - mu[k0 + k]) * inv, 0.0f);
            }
            xs[k][r] = v;
        }
        __syncthreads();
#pragma unroll
        for (int k = 0; k < 32; k++) {
            float a0 = xs[k][tr * 4 + 0];
            float a1 = xs[k][tr * 4 + 1];
            float a2 = xs[k][tr * 4 + 2];
            float a3 = xs[k][tr * 4 + 3];
#pragma unroll
            for (int j = 0; j < 8; j++) {
                float b = ws[k][tc + 16 * j];
                acc[0][j] += a0 * b;
                acc[1][j] += a1 * b;
                acc[2][j] += a2 * b;
                acc[3][j] += a3 * b;
            }
        }
        __syncthreads();
    }
#pragma unroll
    for (int i = 0; i < 4; i++) {
        int gr = row0 + tr * 4 + i;
        if (gr < N) {
            float* Hp = H + ((size_t)gr << 7);
#pragma unroll
            for (int j = 0; j < 8; j++) Hp[tc + 16 * j] = acc[i][j];
        }
    }
}

// ---------------------------------------------------------------------------
// Init aggregation buffer with self-loop term (+ optional bias for final layer):
// out[i,:] = h[i,:] * dinv[i]^2 (+ bias)
__global__ void k_agg_init(const float* __restrict__ h, const float* __restrict__ dinv,
                           float* __restrict__ out, const float* __restrict__ bias, int N) {
    int idx = blockIdx.x * blockDim.x + threadIdx.x;  // over N*32 float4s
    if (idx >= N * 32) return;
    int row = idx >> 5;
    int c4 = idx & 31;
    float s = dinv[row];
    s = s * s;
    float4 v = reinterpret_cast<const float4*>(h)[idx];
    float4 o;
    o.x = v.x * s; o.y = v.y * s; o.z = v.z * s; o.w = v.w * s;
    if (bias) {
        const float4 b = reinterpret_cast<const float4*>(bias)[c4];
        o.x += b.x; o.y += b.y; o.z += b.z; o.w += b.w;
    }
    reinterpret_cast<float4*>(out)[idx] = o;
}

// Warp per edge: out[dst] += h[src] * dinv[src]*dinv[dst], vector RED.
__global__ void k_agg_edges(const float* __restrict__ h, const int* __restrict__ src,
                            const int* __restrict__ dst, const float* __restrict__ dinv,
                            float* __restrict__ out, int E) {
    int w = (blockIdx.x * blockDim.x + threadIdx.x) >> 5;
    int lane = threadIdx.x & 31;
    if (w >= E) return;
    int s = __ldg(&src[w]);
    int d = __ldg(&dst[w]);
    float nrm = __ldg(&dinv[s]) * __ldg(&dinv[d]);
    float4 v = reinterpret_cast<const float4*>(h + ((size_t)s << 7))[lane];
    v.x *= nrm; v.y *= nrm; v.z *= nrm; v.w *= nrm;
    float* op = out + ((size_t)d << 7) + lane * 4;
    asm volatile("red.global.add.v4.f32 [%0], {%1,%2,%3,%4};"
                 :: "l"(op), "f"(v.x), "f"(v.y), "f"(v.z), "f"(v.w)
                 : "memory");
}

// ---------------------------------------------------------------------------
__global__ void k_zero_stats(float* colsum, float* sumsq) {
    int i = threadIdx.x;
    if (i < DD) colsum[i] = 0.0f;
    if (i == 0) sumsq[0] = 0.0f;
}

// One column per thread (blockDim=128), grid-stride over rows.
__global__ void k_stats(const float* __restrict__ x, float* colsum, float* sumsq, int N) {
    int c = threadIdx.x;
    float cs = 0.0f, ss = 0.0f;
    for (int r = blockIdx.x; r < N; r += gridDim.x) {
        float v = x[((size_t)r << 7) + c];
        cs += v;
        ss += v * v;
    }
    atomicAdd(&colsum[c], cs);
    __shared__ float sh[DD];
    sh[c] = ss;
    __syncthreads();
    for (int o = 64; o > 0; o >>= 1) {
        if (c < o) sh[c] += sh[c + o];
        __syncthreads();
    }
    if (c == 0) atomicAdd(sumsq, sh[0]);
}

__global__ void k_finalize(const float* __restrict__ colsum, const float* __restrict__ sumsq,
                           float* mu, float* inv, int N) {
    int c = threadIdx.x;  // 128
    float m = colsum[c] / (float)N;
    mu[c] = m;
    __shared__ float sh[DD];
    sh[c] = m * m;
    __syncthreads();
    for (int o = 64; o > 0; o >>= 1) {
        if (c < o) sh[c] += sh[c + o];
        __syncthreads();
    }
    if (c == 0) {
        float var = sumsq[0] / (float)N - sh[0];
        var = fmaxf(var, 0.0f);
        inv[0] = 1.0f / (sqrtf(var) + 1e-8f);
    }
}

// ---------------------------------------------------------------------------
extern "C" void kernel_launch(void* const* d_in, const int* in_sizes, int n_in,
                              void* d_out, int out_size) {
    const float* x  = (const float*)d_in[0];
    const int* ei   = (const int*)d_in[1];
    const float* W1 = (const float*)d_in[2];
    const float* W3 = (const float*)d_in[6];
    const float* b3 = (const float*)d_in[7];
    const float* W2 = (const float*)d_in[4];
    float* out = (float*)d_out;

    const int N = in_sizes[0] / DD;
    const int E = in_sizes[1] / 2;
    const int* src = ei;
    const int* dst = ei + E;

    float *p_h, *p_agg, *p_deg, *p_dinv, *p_colsum, *p_sumsq, *p_mu, *p_inv;
    cudaGetSymbolAddress((void**)&p_h, g_h);
    cudaGetSymbolAddress((void**)&p_agg, g_agg);
    cudaGetSymbolAddress((void**)&p_deg, g_deg);
    cudaGetSymbolAddress((void**)&p_dinv, g_dinv);
    cudaGetSymbolAddress((void**)&p_colsum, g_colsum);
    cudaGetSymbolAddress((void**)&p_sumsq, g_sumsq);
    cudaGetSymbolAddress((void**)&p_mu, g_mu);
    cudaGetSymbolAddress((void**)&p_inv, g_inv);

    const int BT = 256;
    const int nBlkN = (N + BT - 1) / BT;
    const int nBlkE = (E + BT - 1) / BT;
    const int nBlkEdge = (int)(((long long)E * 32 + BT - 1) / BT);
    const int nBlkND4 = (N * 32 + BT - 1) / BT;
    const int nBlkGemm = (N + 63) / 64;

    // degrees (with self-loops) and d^{-1/2}
    k_deg_init<<<nBlkN, BT>>>(p_deg, N);
    k_deg_count<<<nBlkE, BT>>>(dst, p_deg, E);
    k_dinv<<<nBlkN, BT>>>(p_deg, p_dinv, N);

    // ---- Layer 1 ----
    k_gemm<<<nBlkGemm, BT>>>(x, W1, p_h, p_mu, p_inv, 0, N);
    k_agg_init<<<nBlkND4, BT>>>(p_h, p_dinv, p_agg, nullptr, N);
    k_agg_edges<<<nBlkEdge, BT>>>(p_h, src, dst, p_dinv, p_agg, E);
    k_zero_stats<<<1, DD>>>(p_colsum, p_sumsq);
    k_stats<<<512, DD>>>(p_agg, p_colsum, p_sumsq, N);
    k_finalize<<<1, DD>>>(p_colsum, p_sumsq, p_mu, p_inv, N);

    // ---- Layer 2 (PairNorm+ReLU fused into GEMM X-load) ----
    k_gemm<<<nBlkGemm, BT>>>(p_agg, W2, p_h, p_mu, p_inv, 1, N);
    k_agg_init<<<nBlkND4, BT>>>(p_h, p_dinv, p_agg, nullptr, N);
    k_agg_edges<<<nBlkEdge, BT>>>(p_h, src, dst, p_dinv, p_agg, E);
    k_zero_stats<<<1, DD>>>(p_colsum, p_sumsq);
    k_stats<<<512, DD>>>(p_agg, p_colsum, p_sumsq, N);
    k_finalize<<<1, DD>>>(p_colsum, p_sumsq, p_mu, p_inv, N);

    // ---- Layer 3 (output = agg + b3, directly into d_out) ----
    k_gemm<<<nBlkGemm, BT>>>(p_agg, W3, p_h, p_mu, p_inv, 1, N);
    k_agg_init<<<nBlkND4, BT>>>(p_h, p_dinv, out, b3, N);
    k_agg_edges<<<nBlkEdge, BT>>>(p_h, src, dst, p_dinv, out, E);
}

// round 3
// speedup vs baseline: 2.3985x; 2.3985x over previous
#include <cuda_runtime.h>
#include <math.h>

#define DD 128
#define MAXN 100000
#define MAXE 3200000
#define MAXND (MAXN * DD)

// Scratch (static device globals; allocation is forbidden)
__device__ float g_h[MAXND];       // GEMM output (pre-scaled by dinv[row])
__device__ float g_agg[MAXND];     // aggregation output (input to next layer)
__device__ int   g_degi[MAXN];
__device__ float g_dinv[MAXN];
__device__ int   g_incl[MAXN];     // per-block inclusive scan temp
__device__ int   g_bsum[128];      // block sums for scan
__device__ int   g_rowptr[MAXN + 1];
__device__ int   g_cursor[MAXN];
__device__ int   g_csr[MAXE];      // src indices grouped by dst
__device__ float g_colsum[DD];
__device__ float g_sumsq[1];
__device__ float g_mu[DD];
__device__ float g_inv[1];

// ---------------------------------------------------------------------------
__global__ void k_zero_degi(int* deg, int N) {
    int i = blockIdx.x * blockDim.x + threadIdx.x;
    if (i < N) deg[i] = 0;
}

__global__ void k_deg_count(const int* __restrict__ dst, int* deg, int E) {
    int e = blockIdx.x * blockDim.x + threadIdx.x;
    if (e < E) atomicAdd(&deg[dst[e]], 1);
}

__global__ void k_dinv(const int* __restrict__ deg, float* dinv, int N) {
    int i = blockIdx.x * blockDim.x + threadIdx.x;
    if (i < N) dinv[i] = rsqrtf((float)(deg[i] + 1));  // +1 self-loop
}

// Block-level inclusive scan (1024/block), explicit double-step
__global__ void k_scan1(const int* __restrict__ deg, int* incl, int* bsum, int N) {
    __shared__ int sh[1024];
    int i = blockIdx.x * 1024 + threadIdx.x;
    int v = (i < N) ? deg[i] : 0;
    sh[threadIdx.x] = v;
    __syncthreads();
    for (int o = 1; o < 1024; o <<= 1) {
        int t = (threadIdx.x >= o) ? sh[threadIdx.x - o] : 0;
        __syncthreads();
        sh[threadIdx.x] += t;
        __syncthreads();
    }
    if (i < N) incl[i] = sh[threadIdx.x];
    if (threadIdx.x == 1023) bsum[blockIdx.x] = sh[1023];
}

// Exclusive scan of block sums (single block, up to 128)
__global__ void k_scan2(int* bsum, int nb) {
    __shared__ int sh[128];
    int t = threadIdx.x;
    int v = (t < nb) ? bsum[t] : 0;
    sh[t] = v;
    __syncthreads();
    for (int o = 1; o < 128; o <<= 1) {
        int u = (t >= o) ? sh[t - o] : 0;
        __syncthreads();
        sh[t] += u;
        __syncthreads();
    }
    if (t < nb) bsum[t] = sh[t] - v;  // exclusive
}

__global__ void k_scan3(const int* __restrict__ deg, const int* __restrict__ incl,
                        const int* __restrict__ bsum, int* rowptr, int* cursor, int N) {
    int i = blockIdx.x * blockDim.x + threadIdx.x;
    if (i < N) {
        int ex = incl[i] - deg[i] + bsum[i >> 10];
        rowptr[i] = ex;
        cursor[i] = ex;
        if (i == N - 1) rowptr[N] = ex + deg[i];
    }
}

__global__ void k_scatter(const int* __restrict__ src, const int* __restrict__ dst,
                          int* cursor, int* csr, int E) {
    int e = blockIdx.x * blockDim.x + threadIdx.x;
    if (e < E) {
        int pos = atomicAdd(&cursor[dst[e]], 1);
        csr[pos] = src[e];
    }
}

// ---------------------------------------------------------------------------
// GEMM: H[N,128] = f(X)[N,128] @ W[128,128], scaled by dinv[row] at writeback.
// f = identity (applyNorm=0) or PairNorm+ReLU using (mu, inv) from prev layer.
__global__ void k_gemm(const float* __restrict__ X, const float* __restrict__ W,
                       float* __restrict__ H, const float* __restrict__ mu,
                       const float* __restrict__ invp, const float* __restrict__ dinv,
                       int applyNorm, int N) {
    __shared__ float ws[32][DD];
    __shared__ float xs[32][65];
    const int tid = threadIdx.x;
    const int row0 = blockIdx.x * 64;
    const float inv = applyNorm ? invp[0] : 0.0f;

    float acc[4][8];
#pragma unroll
    for (int i = 0; i < 4; i++)
#pragma unroll
        for (int j = 0; j < 8; j++) acc[i][j] = 0.0f;

    const int tr = tid >> 4;
    const int tc = tid & 15;

    for (int k0 = 0; k0 < DD; k0 += 32) {
        for (int i = tid; i < 32 * DD; i += 256) {
            ws[i >> 7][i & 127] = W[((k0 + (i >> 7)) << 7) + (i & 127)];
        }
        for (int i = tid; i < 64 * 32; i += 256) {
            int r = i >> 5, k = i & 31;
            int gr = row0 + r;
            float v = 0.0f;
            if (gr < N) {
                v = X[((size_t)gr << 7) + k0 + k];
                if (applyNorm) v = fmaxf((v - mu[k0 + k]) * inv, 0.0f);
            }
            xs[k][r] = v;
        }
        __syncthreads();
#pragma unroll
        for (int k = 0; k < 32; k++) {
            float a0 = xs[k][tr * 4 + 0];
            float a1 = xs[k][tr * 4 + 1];
            float a2 = xs[k][tr * 4 + 2];
            float a3 = xs[k][tr * 4 + 3];
#pragma unroll
            for (int j = 0; j < 8; j++) {
                float b = ws[k][tc + 16 * j];
                acc[0][j] += a0 * b;
                acc[1][j] += a1 * b;
                acc[2][j] += a2 * b;
                acc[3][j] += a3 * b;
            }
        }
        __syncthreads();
    }
#pragma unroll
    for (int i = 0; i < 4; i++) {
        int gr = row0 + tr * 4 + i;
        if (gr < N) {
            float dv = dinv[gr];
            float* Hp = H + ((size_t)gr << 7);
#pragma unroll
            for (int j = 0; j < 8; j++) Hp[tc + 16 * j] = acc[i][j] * dv;
        }
    }
}

// ---------------------------------------------------------------------------
// CSR gather aggregation: warp per dst node, grid-stride.
// out[d] = dinv[d] * (h'[d] + sum_{s in nbr(d)} h'[s])  (+ bias)
// Optionally accumulates PairNorm stats (colsum, sumsq) of out.
__global__ void k_aggregate(const float* __restrict__ h, const int* __restrict__ rowptr,
                            const int* __restrict__ csr, const float* __restrict__ dinv,
                            float* __restrict__ out, const float* __restrict__ bias,
                            float* colsum, float* sumsq, int N) {
    __shared__ float s_col[DD];
    __shared__ float s_ss;
    const int doStats = (colsum != nullptr);
    if (doStats) {
        if (threadIdx.x < DD) s_col[threadIdx.x] = 0.0f;
        if (threadIdx.x == 0) s_ss = 0.0f;
        __syncthreads();
    }
    const int lane = threadIdx.x & 31;
    const int warp = (blockIdx.x * blockDim.x + threadIdx.x) >> 5;
    const int nwarps = (gridDim.x * blockDim.x) >> 5;
    float cs0 = 0, cs1 = 0, cs2 = 0, cs3 = 0, ss = 0;

    for (int d = warp; d < N; d += nwarps) {
        float4 acc = reinterpret_cast<const float4*>(h + ((size_t)d << 7))[lane]; // self
        int j = __ldg(&rowptr[d]);
        const int je = __ldg(&rowptr[d + 1]);
        // 8-wide gather for MLP
        for (; j + 8 <= je; j += 8) {
            int s0 = __ldg(&csr[j + 0]);
            int s1 = __ldg(&csr[j + 1]);
            int s2 = __ldg(&csr[j + 2]);
            int s3 = __ldg(&csr[j + 3]);
            int s4 = __ldg(&csr[j + 4]);
            int s5 = __ldg(&csr[j + 5]);
            int s6 = __ldg(&csr[j + 6]);
            int s7 = __ldg(&csr[j + 7]);
            float4 v0 = reinterpret_cast<const float4*>(h + ((size_t)s0 << 7))[lane];
            float4 v1 = reinterpret_cast<const float4*>(h + ((size_t)s1 << 7))[lane];
            float4 v2 = reinterpret_cast<const float4*>(h + ((size_t)s2 << 7))[lane];
            float4 v3 = reinterpret_cast<const float4*>(h + ((size_t)s3 << 7))[lane];
            float4 v4 = reinterpret_cast<const float4*>(h + ((size_t)s4 << 7))[lane];
            float4 v5 = reinterpret_cast<const float4*>(h + ((size_t)s5 << 7))[lane];
            float4 v6 = reinterpret_cast<const float4*>(h + ((size_t)s6 << 7))[lane];
            float4 v7 = reinterpret_cast<const float4*>(h + ((size_t)s7 << 7))[lane];
            acc.x += ((v0.x + v1.x) + (v2.x + v3.x)) + ((v4.x + v5.x) + (v6.x + v7.x));
            acc.y += ((v0.y + v1.y) + (v2.y + v3.y)) + ((v4.y + v5.y) + (v6.y + v7.y));
            acc.z += ((v0.z + v1.z) + (v2.z + v3.z)) + ((v4.z + v5.z) + (v6.z + v7.z));
            acc.w += ((v0.w + v1.w) + (v2.w + v3.w)) + ((v4.w + v5.w) + (v6.w + v7.w));
        }
        for (; j < je; j++) {
            int s = __ldg(&csr[j]);
            float4 v = reinterpret_cast<const float4*>(h + ((size_t)s << 7))[lane];
            acc.x += v.x; acc.y += v.y; acc.z += v.z; acc.w += v.w;
        }
        const float sc = __ldg(&dinv[d]);
        float4 o;
        o.x = acc.x * sc; o.y = acc.y * sc; o.z = acc.z * sc; o.w = acc.w * sc;
        if (bias) {
            const float4 b = reinterpret_cast<const float4*>(bias)[lane];
            o.x += b.x; o.y += b.y; o.z += b.z; o.w += b.w;
        }
        reinterpret_cast<float4*>(out + ((size_t)d << 7))[lane] = o;
        if (doStats) {
            cs0 += o.x; cs1 += o.y; cs2 += o.z; cs3 += o.w;
            ss += o.x * o.x + o.y * o.y + o.z * o.z + o.w * o.w;
        }
    }

    if (doStats) {
        atomicAdd(&s_col[lane * 4 + 0], cs0);
        atomicAdd(&s_col[lane * 4 + 1], cs1);
        atomicAdd(&s_col[lane * 4 + 2], cs2);
        atomicAdd(&s_col[lane * 4 + 3], cs3);
        for (int o = 16; o > 0; o >>= 1) ss += __shfl_down_sync(0xffffffff, ss, o);
        if (lane == 0) atomicAdd(&s_ss, ss);
        __syncthreads();
        if (threadIdx.x < DD) atomicAdd(&colsum[threadIdx.x], s_col[threadIdx.x]);
        if (threadIdx.x == 0) atomicAdd(sumsq, s_ss);
    }
}

// ---------------------------------------------------------------------------
__global__ void k_zero_stats(float* colsum, float* sumsq) {
    int i = threadIdx.x;
    if (i < DD) colsum[i] = 0.0f;
    if (i == 0) sumsq[0] = 0.0f;
}

__global__ void k_finalize(const float* __restrict__ colsum, const float* __restrict__ sumsq,
                           float* mu, float* inv, int N) {
    int c = threadIdx.x;  // 128
    float m = colsum[c] / (float)N;
    mu[c] = m;
    __shared__ float sh[DD];
    sh[c] = m * m;
    __syncthreads();
    for (int o = 64; o > 0; o >>= 1) {
        if (c < o) sh[c] += sh[c + o];
        __syncthreads();
    }
    if (c == 0) {
        float var = sumsq[0] / (float)N - sh[0];
        var = fmaxf(var, 0.0f);
        inv[0] = 1.0f / (sqrtf(var) + 1e-8f);
    }
}

// ---------------------------------------------------------------------------
extern "C" void kernel_launch(void* const* d_in, const int* in_sizes, int n_in,
                              void* d_out, int out_size) {
    const float* x  = (const float*)d_in[0];
    const int* ei   = (const int*)d_in[1];
    const float* W1 = (const float*)d_in[2];
    const float* W2 = (const float*)d_in[4];
    const float* W3 = (const float*)d_in[6];
    const float* b3 = (const float*)d_in[7];
    float* out = (float*)d_out;

    const int N = in_sizes[0] / DD;
    const int E = in_sizes[1] / 2;
    const int* src = ei;
    const int* dst = ei + E;

    float *p_h, *p_agg, *p_dinv, *p_colsum, *p_sumsq, *p_mu, *p_inv;
    int *p_degi, *p_incl, *p_bsum, *p_rowptr, *p_cursor, *p_csr;
    cudaGetSymbolAddress((void**)&p_h, g_h);
    cudaGetSymbolAddress((void**)&p_agg, g_agg);
    cudaGetSymbolAddress((void**)&p_degi, g_degi);
    cudaGetSymbolAddress((void**)&p_dinv, g_dinv);
    cudaGetSymbolAddress((void**)&p_incl, g_incl);
    cudaGetSymbolAddress((void**)&p_bsum, g_bsum);
    cudaGetSymbolAddress((void**)&p_rowptr, g_rowptr);
    cudaGetSymbolAddress((void**)&p_cursor, g_cursor);
    cudaGetSymbolAddress((void**)&p_csr, g_csr);
    cudaGetSymbolAddress((void**)&p_colsum, g_colsum);
    cudaGetSymbolAddress((void**)&p_sumsq, g_sumsq);
    cudaGetSymbolAddress((void**)&p_mu, g_mu);
    cudaGetSymbolAddress((void**)&p_inv, g_inv);

    const int BT = 256;
    const int nBlkN = (N + BT - 1) / BT;
    const int nBlkE = (E + BT - 1) / BT;
    const int nBlkGemm = (N + 63) / 64;
    const int nScan = (N + 1023) / 1024;
    const int nBlkAgg = 1480;

    // --- CSR build (by destination) ---
    k_zero_degi<<<nBlkN, BT>>>(p_degi, N);
    k_deg_count<<<nBlkE, BT>>>(dst, p_degi, E);
    k_dinv<<<nBlkN, BT>>>(p_degi, p_dinv, N);
    k_scan1<<<nScan, 1024>>>(p_degi, p_incl, p_bsum, N);
    k_scan2<<<1, 128>>>(p_bsum, nScan);
    k_scan3<<<nBlkN, BT>>>(p_degi, p_incl, p_bsum, p_rowptr, p_cursor, N);
    k_scatter<<<nBlkE, BT>>>(src, dst, p_cursor, p_csr, E);

    // ---- Layer 1 ----
    k_gemm<<<nBlkGemm, BT>>>(x, W1, p_h, p_mu, p_inv, p_dinv, 0, N);
    k_zero_stats<<<1, DD>>>(p_colsum, p_sumsq);
    k_aggregate<<<nBlkAgg, BT>>>(p_h, p_rowptr, p_csr, p_dinv, p_agg, nullptr,
                                 p_colsum, p_sumsq, N);
    k_finalize<<<1, DD>>>(p_colsum, p_sumsq, p_mu, p_inv, N);

    // ---- Layer 2 (PairNorm+ReLU fused into GEMM X-load) ----
    k_gemm<<<nBlkGemm, BT>>>(p_agg, W2, p_h, p_mu, p_inv, p_dinv, 1, N);
    k_zero_stats<<<1, DD>>>(p_colsum, p_sumsq);
    k_aggregate<<<nBlkAgg, BT>>>(p_h, p_rowptr, p_csr, p_dinv, p_agg, nullptr,
                                 p_colsum, p_sumsq, N);
    k_finalize<<<1, DD>>>(p_colsum, p_sumsq, p_mu, p_inv, N);

    // ---- Layer 3 (output = agg + b3, directly into d_out, no stats) ----
    k_gemm<<<nBlkGemm, BT>>>(p_agg, W3, p_h, p_mu, p_inv, p_dinv, 1, N);
    k_aggregate<<<nBlkAgg, BT>>>(p_h, p_rowptr, p_csr, p_dinv, out, b3,
                                 nullptr, nullptr, N);
}

// round 4
// speedup vs baseline: 2.9351x; 1.2238x over previous
#include <cuda_runtime.h>
#include <cuda_bf16.h>
#include <math.h>

#define DD 128
#define MAXN 100000
#define MAXE 3200000
#define MAXND (MAXN * DD)

// Scratch (static device globals; allocation is forbidden)
__device__ float g_h[MAXND];       // GEMM output (pre-scaled by dinv[row])
__device__ float g_agg[MAXND];     // aggregation output (input to next layer)
__device__ int   g_degi[MAXN];
__device__ float g_dinv[MAXN];
__device__ int   g_incl[MAXN];
__device__ int   g_bsum[128];
__device__ int   g_rowptr[MAXN + 1];
__device__ int   g_cursor[MAXN];
__device__ int   g_csr[MAXE];
__device__ float g_colsum[DD];
__device__ float g_sumsq[1];
__device__ float g_mu[DD];
__device__ float g_inv[1];

// ---------------------------------------------------------------------------
__global__ void k_zero_degi(int* deg, int N) {
    int i = blockIdx.x * blockDim.x + threadIdx.x;
    if (i < N) deg[i] = 0;
}

__global__ void k_deg_count(const int* __restrict__ dst, int* deg, int E) {
    int e = blockIdx.x * blockDim.x + threadIdx.x;
    if (e < E) atomicAdd(&deg[dst[e]], 1);
}

__global__ void k_dinv(const int* __restrict__ deg, float* dinv, int N) {
    int i = blockIdx.x * blockDim.x + threadIdx.x;
    if (i < N) dinv[i] = rsqrtf((float)(deg[i] + 1));  // +1 self-loop
}

__global__ void k_scan1(const int* __restrict__ deg, int* incl, int* bsum, int N) {
    __shared__ int sh[1024];
    int i = blockIdx.x * 1024 + threadIdx.x;
    int v = (i < N) ? deg[i] : 0;
    sh[threadIdx.x] = v;
    __syncthreads();
    for (int o = 1; o < 1024; o <<= 1) {
        int t = (threadIdx.x >= o) ? sh[threadIdx.x - o] : 0;
        __syncthreads();
        sh[threadIdx.x] += t;
        __syncthreads();
    }
    if (i < N) incl[i] = sh[threadIdx.x];
    if (threadIdx.x == 1023) bsum[blockIdx.x] = sh[1023];
}

__global__ void k_scan2(int* bsum, int nb) {
    __shared__ int sh[128];
    int t = threadIdx.x;
    int v = (t < nb) ? bsum[t] : 0;
    sh[t] = v;
    __syncthreads();
    for (int o = 1; o < 128; o <<= 1) {
        int u = (t >= o) ? sh[t - o] : 0;
        __syncthreads();
        sh[t] += u;
        __syncthreads();
    }
    if (t < nb) bsum[t] = sh[t] - v;  // exclusive
}

__global__ void k_scan3(const int* __restrict__ deg, const int* __restrict__ incl,
                        const int* __restrict__ bsum, int* rowptr, int* cursor, int N) {
    int i = blockIdx.x * blockDim.x + threadIdx.x;
    if (i < N) {
        int ex = incl[i] - deg[i] + bsum[i >> 10];
        rowptr[i] = ex;
        cursor[i] = ex;
        if (i == N - 1) rowptr[N] = ex + deg[i];
    }
}

__global__ void k_scatter(const int* __restrict__ src, const int* __restrict__ dst,
                          int* cursor, int* csr, int E) {
    int e = blockIdx.x * blockDim.x + threadIdx.x;
    if (e < E) {
        int pos = atomicAdd(&cursor[dst[e]], 1);
        csr[pos] = src[e];
    }
}

// ---------------------------------------------------------------------------
// Tensor-core GEMM: H[N,128] = f(X)[N,128] @ W[128,128] * dinv[row]
// bf16 3-product split (xh*wh + xh*wl + xl*wh) with fp32 accumulation.
// Block: 256 threads (8 warps), 128 rows x 128 cols. W staged once (hi+lo).
#define W_STRIDE 136   // bf16 elems per n-row of staged W (conflict-free B frags)
#define X_STRIDE 24    // bf16 elems per row of staged X chunk (conflict-free A frags)

__device__ __forceinline__ void mma16816(float* c, const unsigned* a, const unsigned* b) {
    asm volatile(
        "mma.sync.aligned.m16n8k16.row.col.f32.bf16.bf16.f32 "
        "{%0,%1,%2,%3},{%4,%5,%6,%7},{%8,%9},{%0,%1,%2,%3};"
        : "+f"(c[0]), "+f"(c[1]), "+f"(c[2]), "+f"(c[3])
        : "r"(a[0]), "r"(a[1]), "r"(a[2]), "r"(a[3]), "r"(b[0]), "r"(b[1]));
}

__global__ void __launch_bounds__(256, 2)
k_gemm_tc(const float* __restrict__ X, const float* __restrict__ W,
          float* __restrict__ H, const float* __restrict__ mu,
          const float* __restrict__ invp, const float* __restrict__ dinv,
          int applyNorm, int N) {
    extern __shared__ __nv_bfloat16 smem[];
    __nv_bfloat16* wh = smem;                       // [128][W_STRIDE]
    __nv_bfloat16* wl = wh + 128 * W_STRIDE;
    __nv_bfloat16* xh = wl + 128 * W_STRIDE;        // [128][X_STRIDE]
    __nv_bfloat16* xl = xh + 128 * X_STRIDE;

    const int tid = threadIdx.x;
    const int warp = tid >> 5;
    const int lane = tid & 31;
    const int g = lane >> 2;       // group row / B col
    const int tg = lane & 3;       // thread-in-group
    const int row0 = blockIdx.x * 128;
    const float inv = applyNorm ? invp[0] : 0.0f;

    // Stage W (hi + lo), transposed to [n][k]
    for (int i = tid; i < DD * DD; i += 256) {
        int k = i >> 7, n = i & 127;
        float w = W[i];
        __nv_bfloat16 hi = __float2bfloat16(w);
        float lo = w - __bfloat162float(hi);
        wh[n * W_STRIDE + k] = hi;
        wl[n * W_STRIDE + k] = __float2bfloat16(lo);
    }

    float c[16][4];
#pragma unroll
    for (int i = 0; i < 16; i++)
#pragma unroll
        for (int j = 0; j < 4; j++) c[i][j] = 0.0f;

    const int arow = warp * 16;

    for (int kc = 0; kc < DD; kc += 16) {
        __syncthreads();   // protect previous chunk's consumption / W on first iter
        // Stage X chunk [128 rows][16 k], fused PairNorm+ReLU, split hi/lo
        for (int i = tid; i < 128 * 16; i += 256) {
            int r = i >> 4, kk = i & 15;
            int gr = row0 + r;
            float v = 0.0f;
            if (gr < N) {
                v = X[((size_t)gr << 7) + kc + kk];
                if (applyNorm) v = fmaxf((v - mu[kc + kk]) * inv, 0.0f);
            }
            __nv_bfloat16 hi = __float2bfloat16(v);
            float lo = v - __bfloat162float(hi);
            xh[r * X_STRIDE + kk] = hi;
            xl[r * X_STRIDE + kk] = __float2bfloat16(lo);
        }
        __syncthreads();

        // A fragments for this warp's 16 rows
        unsigned ah[4], al[4];
        {
            const __nv_bfloat16* ph = xh + (arow + g) * X_STRIDE + 2 * tg;
            const __nv_bfloat16* pl = xl + (arow + g) * X_STRIDE + 2 * tg;
            ah[0] = *(const unsigned*)(ph);
            ah[1] = *(const unsigned*)(ph + 8 * X_STRIDE);
            ah[2] = *(const unsigned*)(ph + 8);
            ah[3] = *(const unsigned*)(ph + 8 * X_STRIDE + 8);
            al[0] = *(const unsigned*)(pl);
            al[1] = *(const unsigned*)(pl + 8 * X_STRIDE);
            al[2] = *(const unsigned*)(pl + 8);
            al[3] = *(const unsigned*)(pl + 8 * X_STRIDE + 8);
        }

#pragma unroll
        for (int nt = 0; nt < 16; nt++) {
            unsigned bh[2], bl[2];
            const __nv_bfloat16* pbh = wh + (nt * 8 + g) * W_STRIDE + kc + 2 * tg;
            const __nv_bfloat16* pbl = wl + (nt * 8 + g) * W_STRIDE + kc + 2 * tg;
            bh[0] = *(const unsigned*)(pbh);
            bh[1] = *(const unsigned*)(pbh + 8);
            bl[0] = *(const unsigned*)(pbl);
            bl[1] = *(const unsigned*)(pbl + 8);
            mma16816(c[nt], ah, bh);
            mma16816(c[nt], ah, bl);
            mma16816(c[nt], al, bh);
        }
    }

    // Epilogue: scale by dinv[row], store float2 per fragment row
    const int r0 = row0 + arow + g;
    const int r1 = r0 + 8;
    const float dv0 = (r0 < N) ? dinv[r0] : 0.0f;
    const float dv1 = (r1 < N) ? dinv[r1] : 0.0f;
#pragma unroll
    for (int nt = 0; nt < 16; nt++) {
        int col = nt * 8 + 2 * tg;
        if (r0 < N) {
            float2 v = make_float2(c[nt][0] * dv0, c[nt][1] * dv0);
            *(float2*)(H + ((size_t)r0 << 7) + col) = v;
        }
        if (r1 < N) {
            float2 v = make_float2(c[nt][2] * dv1, c[nt][3] * dv1);
            *(float2*)(H + ((size_t)r1 << 7) + col) = v;
        }
    }
}

// ---------------------------------------------------------------------------
// CSR gather aggregation: warp per dst node, grid-stride.
__global__ void k_aggregate(const float* __restrict__ h, const int* __restrict__ rowptr,
                            const int* __restrict__ csr, const float* __restrict__ dinv,
                            float* __restrict__ out, const float* __restrict__ bias,
                            float* colsum, float* sumsq, int N) {
    __shared__ float s_col[DD];
    __shared__ float s_ss;
    const int doStats = (colsum != nullptr);
    if (doStats) {
        if (threadIdx.x < DD) s_col[threadIdx.x] = 0.0f;
        if (threadIdx.x == 0) s_ss = 0.0f;
        __syncthreads();
    }
    const int lane = threadIdx.x & 31;
    const int warp = (blockIdx.x * blockDim.x + threadIdx.x) >> 5;
    const int nwarps = (gridDim.x * blockDim.x) >> 5;
    float cs0 = 0, cs1 = 0, cs2 = 0, cs3 = 0, ss = 0;

    for (int d = warp; d < N; d += nwarps) {
        float4 acc = reinterpret_cast<const float4*>(h + ((size_t)d << 7))[lane]; // self
        int j = __ldg(&rowptr[d]);
        const int je = __ldg(&rowptr[d + 1]);
        for (; j + 8 <= je; j += 8) {
            int s0 = __ldg(&csr[j + 0]);
            int s1 = __ldg(&csr[j + 1]);
            int s2 = __ldg(&csr[j + 2]);
            int s3 = __ldg(&csr[j + 3]);
            int s4 = __ldg(&csr[j + 4]);
            int s5 = __ldg(&csr[j + 5]);
            int s6 = __ldg(&csr[j + 6]);
            int s7 = __ldg(&csr[j + 7]);
            float4 v0 = reinterpret_cast<const float4*>(h + ((size_t)s0 << 7))[lane];
            float4 v1 = reinterpret_cast<const float4*>(h + ((size_t)s1 << 7))[lane];
            float4 v2 = reinterpret_cast<const float4*>(h + ((size_t)s2 << 7))[lane];
            float4 v3 = reinterpret_cast<const float4*>(h + ((size_t)s3 << 7))[lane];
            float4 v4 = reinterpret_cast<const float4*>(h + ((size_t)s4 << 7))[lane];
            float4 v5 = reinterpret_cast<const float4*>(h + ((size_t)s5 << 7))[lane];
            float4 v6 = reinterpret_cast<const float4*>(h + ((size_t)s6 << 7))[lane];
            float4 v7 = reinterpret_cast<const float4*>(h + ((size_t)s7 << 7))[lane];
            acc.x += ((v0.x + v1.x) + (v2.x + v3.x)) + ((v4.x + v5.x) + (v6.x + v7.x));
            acc.y += ((v0.y + v1.y) + (v2.y + v3.y)) + ((v4.y + v5.y) + (v6.y + v7.y));
            acc.z += ((v0.z + v1.z) + (v2.z + v3.z)) + ((v4.z + v5.z) + (v6.z + v7.z));
            acc.w += ((v0.w + v1.w) + (v2.w + v3.w)) + ((v4.w + v5.w) + (v6.w + v7.w));
        }
        for (; j < je; j++) {
            int s = __ldg(&csr[j]);
            float4 v = reinterpret_cast<const float4*>(h + ((size_t)s << 7))[lane];
            acc.x += v.x; acc.y += v.y; acc.z += v.z; acc.w += v.w;
        }
        const float sc = __ldg(&dinv[d]);
        float4 o;
        o.x = acc.x * sc; o.y = acc.y * sc; o.z = acc.z * sc; o.w = acc.w * sc;
        if (bias) {
            const float4 b = reinterpret_cast<const float4*>(bias)[lane];
            o.x += b.x; o.y += b.y; o.z += b.z; o.w += b.w;
        }
        reinterpret_cast<float4*>(out + ((size_t)d << 7))[lane] = o;
        if (doStats) {
            cs0 += o.x; cs1 += o.y; cs2 += o.z; cs3 += o.w;
            ss += o.x * o.x + o.y * o.y + o.z * o.z + o.w * o.w;
        }
    }

    if (doStats) {
        atomicAdd(&s_col[lane * 4 + 0], cs0);
        atomicAdd(&s_col[lane * 4 + 1], cs1);
        atomicAdd(&s_col[lane * 4 + 2], cs2);
        atomicAdd(&s_col[lane * 4 + 3], cs3);
        for (int o = 16; o > 0; o >>= 1) ss += __shfl_down_sync(0xffffffff, ss, o);
        if (lane == 0) atomicAdd(&s_ss, ss);
        __syncthreads();
        if (threadIdx.x < DD) atomicAdd(&colsum[threadIdx.x], s_col[threadIdx.x]);
        if (threadIdx.x == 0) atomicAdd(sumsq, s_ss);
    }
}

// ---------------------------------------------------------------------------
__global__ void k_zero_stats(float* colsum, float* sumsq) {
    int i = threadIdx.x;
    if (i < DD) colsum[i] = 0.0f;
    if (i == 0) sumsq[0] = 0.0f;
}

__global__ void k_finalize(const float* __restrict__ colsum, const float* __restrict__ sumsq,
                           float* mu, float* inv, int N) {
    int c = threadIdx.x;  // 128
    float m = colsum[c] / (float)N;
    mu[c] = m;
    __shared__ float sh[DD];
    sh[c] = m * m;
    __syncthreads();
    for (int o = 64; o > 0; o >>= 1) {
        if (c < o) sh[c] += sh[c + o];
        __syncthreads();
    }
    if (c == 0) {
        float var = sumsq[0] / (float)N - sh[0];
        var = fmaxf(var, 0.0f);
        inv[0] = 1.0f / (sqrtf(var) + 1e-8f);
    }
}

// ---------------------------------------------------------------------------
extern "C" void kernel_launch(void* const* d_in, const int* in_sizes, int n_in,
                              void* d_out, int out_size) {
    const float* x  = (const float*)d_in[0];
    const int* ei   = (const int*)d_in[1];
    const float* W1 = (const float*)d_in[2];
    const float* W2 = (const float*)d_in[4];
    const float* W3 = (const float*)d_in[6];
    const float* b3 = (const float*)d_in[7];
    float* out = (float*)d_out;

    const int N = in_sizes[0] / DD;
    const int E = in_sizes[1] / 2;
    const int* src = ei;
    const int* dst = ei + E;

    float *p_h, *p_agg, *p_dinv, *p_colsum, *p_sumsq, *p_mu, *p_inv;
    int *p_degi, *p_incl, *p_bsum, *p_rowptr, *p_cursor, *p_csr;
    cudaGetSymbolAddress((void**)&p_h, g_h);
    cudaGetSymbolAddress((void**)&p_agg, g_agg);
    cudaGetSymbolAddress((void**)&p_degi, g_degi);
    cudaGetSymbolAddress((void**)&p_dinv, g_dinv);
    cudaGetSymbolAddress((void**)&p_incl, g_incl);
    cudaGetSymbolAddress((void**)&p_bsum, g_bsum);
    cudaGetSymbolAddress((void**)&p_rowptr, g_rowptr);
    cudaGetSymbolAddress((void**)&p_cursor, g_cursor);
    cudaGetSymbolAddress((void**)&p_csr, g_csr);
    cudaGetSymbolAddress((void**)&p_colsum, g_colsum);
    cudaGetSymbolAddress((void**)&p_sumsq, g_sumsq);
    cudaGetSymbolAddress((void**)&p_mu, g_mu);
    cudaGetSymbolAddress((void**)&p_inv, g_inv);

    const int SMEM_TC = (2 * 128 * W_STRIDE + 2 * 128 * X_STRIDE) * 2; // bytes
    static int attrSet = 0;
    if (!attrSet) {
        cudaFuncSetAttribute(k_gemm_tc, cudaFuncAttributeMaxDynamicSharedMemorySize,
                             SMEM_TC);
        attrSet = 1;
    }

    const int BT = 256;
    const int nBlkN = (N + BT - 1) / BT;
    const int nBlkE = (E + BT - 1) / BT;
    const int nBlkGemm = (N + 127) / 128;
    const int nScan = (N + 1023) / 1024;
    const int nBlkAgg = 1480;

    // --- CSR build (by destination) ---
    k_zero_degi<<<nBlkN, BT>>>(p_degi, N);
    k_deg_count<<<nBlkE, BT>>>(dst, p_degi, E);
    k_dinv<<<nBlkN, BT>>>(p_degi, p_dinv, N);
    k_scan1<<<nScan, 1024>>>(p_degi, p_incl, p_bsum, N);
    k_scan2<<<1, 128>>>(p_bsum, nScan);
    k_scan3<<<nBlkN, BT>>>(p_degi, p_incl, p_bsum, p_rowptr, p_cursor, N);
    k_scatter<<<nBlkE, BT>>>(src, dst, p_cursor, p_csr, E);

    // ---- Layer 1 ----
    k_gemm_tc<<<nBlkGemm, BT, SMEM_TC>>>(x, W1, p_h, p_mu, p_inv, p_dinv, 0, N);
    k_zero_stats<<<1, DD>>>(p_colsum, p_sumsq);
    k_aggregate<<<nBlkAgg, BT>>>(p_h, p_rowptr, p_csr, p_dinv, p_agg, nullptr,
                                 p_colsum, p_sumsq, N);
    k_finalize<<<1, DD>>>(p_colsum, p_sumsq, p_mu, p_inv, N);

    // ---- Layer 2 (PairNorm+ReLU fused into GEMM X-load) ----
    k_gemm_tc<<<nBlkGemm, BT, SMEM_TC>>>(p_agg, W2, p_h, p_mu, p_inv, p_dinv, 1, N);
    k_zero_stats<<<1, DD>>>(p_colsum, p_sumsq);
    k_aggregate<<<nBlkAgg, BT>>>(p_h, p_rowptr, p_csr, p_dinv, p_agg, nullptr,
                                 p_colsum, p_sumsq, N);
    k_finalize<<<1, DD>>>(p_colsum, p_sumsq, p_mu, p_inv, N);

    // ---- Layer 3 (output = agg + b3, directly into d_out, no stats) ----
    k_gemm_tc<<<nBlkGemm, BT, SMEM_TC>>>(p_agg, W3, p_h, p_mu, p_inv, p_dinv, 1, N);
    k_aggregate<<<nBlkAgg, BT>>>(p_h, p_rowptr, p_csr, p_dinv, out, b3,
                                 nullptr, nullptr, N);
}

// round 5
// speedup vs baseline: 3.1204x; 1.0631x over previous
#include <cuda_runtime.h>
#include <cuda_bf16.h>
#include <cuda_fp16.h>
#include <math.h>

#define DD 128
#define MAXN 100000
#define MAXE 3200000
#define MAXND (MAXN * DD)

// Scratch (static device globals; allocation is forbidden)
__device__ __half g_h[MAXND];      // GEMM output in fp16 (pre-scaled by dinv[row])
__device__ float g_agg[MAXND];     // aggregation output (input to next layer)
__device__ int   g_degi[MAXN];
__device__ float g_dinv[MAXN];
__device__ int   g_incl[MAXN];
__device__ int   g_bsum[128];
__device__ int   g_rowptr[MAXN + 1];
__device__ int   g_cursor[MAXN];
__device__ int   g_csr[MAXE];
__device__ float g_colsum[DD];
__device__ float g_sumsq[1];
__device__ float g_mu[DD];
__device__ float g_inv[1];

// ---------------------------------------------------------------------------
__global__ void k_zero_degi(int* deg, int N) {
    int i = blockIdx.x * blockDim.x + threadIdx.x;
    if (i < N) deg[i] = 0;
}

__global__ void k_deg_count(const int* __restrict__ dst, int* deg, int E) {
    int e = blockIdx.x * blockDim.x + threadIdx.x;
    if (e < E) atomicAdd(&deg[dst[e]], 1);
}

__global__ void k_dinv(const int* __restrict__ deg, float* dinv, int N) {
    int i = blockIdx.x * blockDim.x + threadIdx.x;
    if (i < N) dinv[i] = rsqrtf((float)(deg[i] + 1));  // +1 self-loop
}

__global__ void k_scan1(const int* __restrict__ deg, int* incl, int* bsum, int N) {
    __shared__ int sh[1024];
    int i = blockIdx.x * 1024 + threadIdx.x;
    int v = (i < N) ? deg[i] : 0;
    sh[threadIdx.x] = v;
    __syncthreads();
    for (int o = 1; o < 1024; o <<= 1) {
        int t = (threadIdx.x >= o) ? sh[threadIdx.x - o] : 0;
        __syncthreads();
        sh[threadIdx.x] += t;
        __syncthreads();
    }
    if (i < N) incl[i] = sh[threadIdx.x];
    if (threadIdx.x == 1023) bsum[blockIdx.x] = sh[1023];
}

__global__ void k_scan2(int* bsum, int nb) {
    __shared__ int sh[128];
    int t = threadIdx.x;
    int v = (t < nb) ? bsum[t] : 0;
    sh[t] = v;
    __syncthreads();
    for (int o = 1; o < 128; o <<= 1) {
        int u = (t >= o) ? sh[t - o] : 0;
        __syncthreads();
        sh[t] += u;
        __syncthreads();
    }
    if (t < nb) bsum[t] = sh[t] - v;  // exclusive
}

__global__ void k_scan3(const int* __restrict__ deg, const int* __restrict__ incl,
                        const int* __restrict__ bsum, int* rowptr, int* cursor, int N) {
    int i = blockIdx.x * blockDim.x + threadIdx.x;
    if (i < N) {
        int ex = incl[i] - deg[i] + bsum[i >> 10];
        rowptr[i] = ex;
        cursor[i] = ex;
        if (i == N - 1) rowptr[N] = ex + deg[i];
    }
}

__global__ void k_scatter(const int* __restrict__ src, const int* __restrict__ dst,
                          int* cursor, int* csr, int E) {
    int e = blockIdx.x * blockDim.x + threadIdx.x;
    if (e < E) {
        int pos = atomicAdd(&cursor[dst[e]], 1);
        csr[pos] = src[e];
    }
}

// ---------------------------------------------------------------------------
// Tensor-core GEMM: H[N,128] = f(X)[N,128] @ W[128,128] * dinv[row], fp16 out.
// bf16 3-product split (xh*wh + xh*wl + xl*wh) with fp32 accumulation.
#define W_STRIDE 136
#define X_STRIDE 24

__device__ __forceinline__ void mma16816(float* c, const unsigned* a, const unsigned* b) {
    asm volatile(
        "mma.sync.aligned.m16n8k16.row.col.f32.bf16.bf16.f32 "
        "{%0,%1,%2,%3},{%4,%5,%6,%7},{%8,%9},{%0,%1,%2,%3};"
        : "+f"(c[0]), "+f"(c[1]), "+f"(c[2]), "+f"(c[3])
        : "r"(a[0]), "r"(a[1]), "r"(a[2]), "r"(a[3]), "r"(b[0]), "r"(b[1]));
}

__global__ void __launch_bounds__(256, 2)
k_gemm_tc(const float* __restrict__ X, const float* __restrict__ W,
          __half* __restrict__ H, const float* __restrict__ mu,
          const float* __restrict__ invp, const float* __restrict__ dinv,
          int applyNorm, int N) {
    extern __shared__ __nv_bfloat16 smem[];
    __nv_bfloat16* wh = smem;                       // [128][W_STRIDE]
    __nv_bfloat16* wl = wh + 128 * W_STRIDE;
    __nv_bfloat16* xh = wl + 128 * W_STRIDE;        // [128][X_STRIDE]
    __nv_bfloat16* xl = xh + 128 * X_STRIDE;

    const int tid = threadIdx.x;
    const int warp = tid >> 5;
    const int lane = tid & 31;
    const int g = lane >> 2;
    const int tg = lane & 3;
    const int row0 = blockIdx.x * 128;
    const float inv = applyNorm ? invp[0] : 0.0f;

    // Stage W (hi + lo), transposed to [n][k]
    for (int i = tid; i < DD * DD; i += 256) {
        int k = i >> 7, n = i & 127;
        float w = W[i];
        __nv_bfloat16 hi = __float2bfloat16(w);
        float lo = w - __bfloat162float(hi);
        wh[n * W_STRIDE + k] = hi;
        wl[n * W_STRIDE + k] = __float2bfloat16(lo);
    }

    float c[16][4];
#pragma unroll
    for (int i = 0; i < 16; i++)
#pragma unroll
        for (int j = 0; j < 4; j++) c[i][j] = 0.0f;

    const int arow = warp * 16;

    for (int kc = 0; kc < DD; kc += 16) {
        __syncthreads();
        for (int i = tid; i < 128 * 16; i += 256) {
            int r = i >> 4, kk = i & 15;
            int gr = row0 + r;
            float v = 0.0f;
            if (gr < N) {
                v = X[((size_t)gr << 7) + kc + kk];
                if (applyNorm) v = fmaxf((v - mu[kc + kk]) * inv, 0.0f);
            }
            __nv_bfloat16 hi = __float2bfloat16(v);
            float lo = v - __bfloat162float(hi);
            xh[r * X_STRIDE + kk] = hi;
            xl[r * X_STRIDE + kk] = __float2bfloat16(lo);
        }
        __syncthreads();

        unsigned ah[4], al[4];
        {
            const __nv_bfloat16* ph = xh + (arow + g) * X_STRIDE + 2 * tg;
            const __nv_bfloat16* pl = xl + (arow + g) * X_STRIDE + 2 * tg;
            ah[0] = *(const unsigned*)(ph);
            ah[1] = *(const unsigned*)(ph + 8 * X_STRIDE);
            ah[2] = *(const unsigned*)(ph + 8);
            ah[3] = *(const unsigned*)(ph + 8 * X_STRIDE + 8);
            al[0] = *(const unsigned*)(pl);
            al[1] = *(const unsigned*)(pl + 8 * X_STRIDE);
            al[2] = *(const unsigned*)(pl + 8);
            al[3] = *(const unsigned*)(pl + 8 * X_STRIDE + 8);
        }

#pragma unroll
        for (int nt = 0; nt < 16; nt++) {
            unsigned bh[2], bl[2];
            const __nv_bfloat16* pbh = wh + (nt * 8 + g) * W_STRIDE + kc + 2 * tg;
            const __nv_bfloat16* pbl = wl + (nt * 8 + g) * W_STRIDE + kc + 2 * tg;
            bh[0] = *(const unsigned*)(pbh);
            bh[1] = *(const unsigned*)(pbh + 8);
            bl[0] = *(const unsigned*)(pbl);
            bl[1] = *(const unsigned*)(pbl + 8);
            mma16816(c[nt], ah, bh);
            mma16816(c[nt], ah, bl);
            mma16816(c[nt], al, bh);
        }
    }

    // Epilogue: scale by dinv[row], store half2
    const int r0 = row0 + arow + g;
    const int r1 = r0 + 8;
    const float dv0 = (r0 < N) ? dinv[r0] : 0.0f;
    const float dv1 = (r1 < N) ? dinv[r1] : 0.0f;
#pragma unroll
    for (int nt = 0; nt < 16; nt++) {
        int col = nt * 8 + 2 * tg;
        if (r0 < N)
            *(__half2*)(H + ((size_t)r0 << 7) + col) =
                __floats2half2_rn(c[nt][0] * dv0, c[nt][1] * dv0);
        if (r1 < N)
            *(__half2*)(H + ((size_t)r1 << 7) + col) =
                __floats2half2_rn(c[nt][2] * dv1, c[nt][3] * dv1);
    }
}

// ---------------------------------------------------------------------------
// CSR gather aggregation: warp per dst node, grid-stride, fp16 rows -> fp32 acc.
// Each lane handles columns [lane*4, lane*4+4) via one uint2 (4 halves) per row.
__device__ __forceinline__ void acc_row(float4& acc, const uint2* hp, int s, int lane) {
    uint2 u = __ldg(&hp[((size_t)s << 5) + lane]);
    __half2 p0 = *reinterpret_cast<__half2*>(&u.x);
    __half2 p1 = *reinterpret_cast<__half2*>(&u.y);
    float2 f0 = __half22float2(p0);
    float2 f1 = __half22float2(p1);
    acc.x += f0.x; acc.y += f0.y; acc.z += f1.x; acc.w += f1.y;
}

__global__ void k_aggregate(const __half* __restrict__ h, const int* __restrict__ rowptr,
                            const int* __restrict__ csr, const float* __restrict__ dinv,
                            float* __restrict__ out, const float* __restrict__ bias,
                            float* colsum, float* sumsq, int N) {
    __shared__ float s_col[DD];
    __shared__ float s_ss;
    const int doStats = (colsum != nullptr);
    if (doStats) {
        if (threadIdx.x < DD) s_col[threadIdx.x] = 0.0f;
        if (threadIdx.x == 0) s_ss = 0.0f;
        __syncthreads();
    }
    const int lane = threadIdx.x & 31;
    const int warp = (blockIdx.x * blockDim.x + threadIdx.x) >> 5;
    const int nwarps = (gridDim.x * blockDim.x) >> 5;
    const uint2* hp = reinterpret_cast<const uint2*>(h);
    float cs0 = 0, cs1 = 0, cs2 = 0, cs3 = 0, ss = 0;

    for (int d = warp; d < N; d += nwarps) {
        float4 acc = make_float4(0.f, 0.f, 0.f, 0.f);
        acc_row(acc, hp, d, lane);  // self
        int j = __ldg(&rowptr[d]);
        const int je = __ldg(&rowptr[d + 1]);
        for (; j + 8 <= je; j += 8) {
            int s0 = __ldg(&csr[j + 0]);
            int s1 = __ldg(&csr[j + 1]);
            int s2 = __ldg(&csr[j + 2]);
            int s3 = __ldg(&csr[j + 3]);
            int s4 = __ldg(&csr[j + 4]);
            int s5 = __ldg(&csr[j + 5]);
            int s6 = __ldg(&csr[j + 6]);
            int s7 = __ldg(&csr[j + 7]);
            uint2 u0 = __ldg(&hp[((size_t)s0 << 5) + lane]);
            uint2 u1 = __ldg(&hp[((size_t)s1 << 5) + lane]);
            uint2 u2 = __ldg(&hp[((size_t)s2 << 5) + lane]);
            uint2 u3 = __ldg(&hp[((size_t)s3 << 5) + lane]);
            uint2 u4 = __ldg(&hp[((size_t)s4 << 5) + lane]);
            uint2 u5 = __ldg(&hp[((size_t)s5 << 5) + lane]);
            uint2 u6 = __ldg(&hp[((size_t)s6 << 5) + lane]);
            uint2 u7 = __ldg(&hp[((size_t)s7 << 5) + lane]);
#define ACCU(u) { \
            float2 f0 = __half22float2(*reinterpret_cast<__half2*>(&u.x)); \
            float2 f1 = __half22float2(*reinterpret_cast<__half2*>(&u.y)); \
            acc.x += f0.x; acc.y += f0.y; acc.z += f1.x; acc.w += f1.y; }
            ACCU(u0) ACCU(u1) ACCU(u2) ACCU(u3)
            ACCU(u4) ACCU(u5) ACCU(u6) ACCU(u7)
#undef ACCU
        }
        for (; j < je; j++) {
            int s = __ldg(&csr[j]);
            acc_row(acc, hp, s, lane);
        }
        const float sc = __ldg(&dinv[d]);
        float4 o;
        o.x = acc.x * sc; o.y = acc.y * sc; o.z = acc.z * sc; o.w = acc.w * sc;
        if (bias) {
            const float4 b = reinterpret_cast<const float4*>(bias)[lane];
            o.x += b.x; o.y += b.y; o.z += b.z; o.w += b.w;
        }
        reinterpret_cast<float4*>(out + ((size_t)d << 7))[lane] = o;
        if (doStats) {
            cs0 += o.x; cs1 += o.y; cs2 += o.z; cs3 += o.w;
            ss += o.x * o.x + o.y * o.y + o.z * o.z + o.w * o.w;
        }
    }

    if (doStats) {
        atomicAdd(&s_col[lane * 4 + 0], cs0);
        atomicAdd(&s_col[lane * 4 + 1], cs1);
        atomicAdd(&s_col[lane * 4 + 2], cs2);
        atomicAdd(&s_col[lane * 4 + 3], cs3);
        for (int o = 16; o > 0; o >>= 1) ss += __shfl_down_sync(0xffffffff, ss, o);
        if (lane == 0) atomicAdd(&s_ss, ss);
        __syncthreads();
        if (threadIdx.x < DD) atomicAdd(&colsum[threadIdx.x], s_col[threadIdx.x]);
        if (threadIdx.x == 0) atomicAdd(sumsq, s_ss);
    }
}

// ---------------------------------------------------------------------------
__global__ void k_zero_stats(float* colsum, float* sumsq) {
    int i = threadIdx.x;
    if (i < DD) colsum[i] = 0.0f;
    if (i == 0) sumsq[0] = 0.0f;
}

__global__ void k_finalize(const float* __restrict__ colsum, const float* __restrict__ sumsq,
                           float* mu, float* inv, int N) {
    int c = threadIdx.x;  // 128
    float m = colsum[c] / (float)N;
    mu[c] = m;
    __shared__ float sh[DD];
    sh[c] = m * m;
    __syncthreads();
    for (int o = 64; o > 0; o >>= 1) {
        if (c < o) sh[c] += sh[c + o];
        __syncthreads();
    }
    if (c == 0) {
        float var = sumsq[0] / (float)N - sh[0];
        var = fmaxf(var, 0.0f);
        inv[0] = 1.0f / (sqrtf(var) + 1e-8f);
    }
}

// ---------------------------------------------------------------------------
extern "C" void kernel_launch(void* const* d_in, const int* in_sizes, int n_in,
                              void* d_out, int out_size) {
    const float* x  = (const float*)d_in[0];
    const int* ei   = (const int*)d_in[1];
    const float* W1 = (const float*)d_in[2];
    const float* W2 = (const float*)d_in[4];
    const float* W3 = (const float*)d_in[6];
    const float* b3 = (const float*)d_in[7];
    float* out = (float*)d_out;

    const int N = in_sizes[0] / DD;
    const int E = in_sizes[1] / 2;
    const int* src = ei;
    const int* dst = ei + E;

    float *p_agg, *p_dinv, *p_colsum, *p_sumsq, *p_mu, *p_inv;
    __half* p_h;
    int *p_degi, *p_incl, *p_bsum, *p_rowptr, *p_cursor, *p_csr;
    cudaGetSymbolAddress((void**)&p_h, g_h);
    cudaGetSymbolAddress((void**)&p_agg, g_agg);
    cudaGetSymbolAddress((void**)&p_degi, g_degi);
    cudaGetSymbolAddress((void**)&p_dinv, g_dinv);
    cudaGetSymbolAddress((void**)&p_incl, g_incl);
    cudaGetSymbolAddress((void**)&p_bsum, g_bsum);
    cudaGetSymbolAddress((void**)&p_rowptr, g_rowptr);
    cudaGetSymbolAddress((void**)&p_cursor, g_cursor);
    cudaGetSymbolAddress((void**)&p_csr, g_csr);
    cudaGetSymbolAddress((void**)&p_colsum, g_colsum);
    cudaGetSymbolAddress((void**)&p_sumsq, g_sumsq);
    cudaGetSymbolAddress((void**)&p_mu, g_mu);
    cudaGetSymbolAddress((void**)&p_inv, g_inv);

    const int SMEM_TC = (2 * 128 * W_STRIDE + 2 * 128 * X_STRIDE) * 2; // bytes
    static int attrSet = 0;
    if (!attrSet) {
        cudaFuncSetAttribute(k_gemm_tc, cudaFuncAttributeMaxDynamicSharedMemorySize,
                             SMEM_TC);
        attrSet = 1;
    }

    const int BT = 256;
    const int nBlkN = (N + BT - 1) / BT;
    const int nBlkE = (E + BT - 1) / BT;
    const int nBlkGemm = (N + 127) / 128;
    const int nScan = (N + 1023) / 1024;
    const int nBlkAgg = 1480;

    // --- CSR build (by destination) ---
    k_zero_degi<<<nBlkN, BT>>>(p_degi, N);
    k_deg_count<<<nBlkE, BT>>>(dst, p_degi, E);
    k_dinv<<<nBlkN, BT>>>(p_degi, p_dinv, N);
    k_scan1<<<nScan, 1024>>>(p_degi, p_incl, p_bsum, N);
    k_scan2<<<1, 128>>>(p_bsum, nScan);
    k_scan3<<<nBlkN, BT>>>(p_degi, p_incl, p_bsum, p_rowptr, p_cursor, N);
    k_scatter<<<nBlkE, BT>>>(src, dst, p_cursor, p_csr, E);

    // ---- Layer 1 ----
    k_gemm_tc<<<nBlkGemm, BT, SMEM_TC>>>(x, W1, p_h, p_mu, p_inv, p_dinv, 0, N);
    k_zero_stats<<<1, DD>>>(p_colsum, p_sumsq);
    k_aggregate<<<nBlkAgg, BT>>>(p_h, p_rowptr, p_csr, p_dinv, p_agg, nullptr,
                                 p_colsum, p_sumsq, N);
    k_finalize<<<1, DD>>>(p_colsum, p_sumsq, p_mu, p_inv, N);

    // ---- Layer 2 (PairNorm+ReLU fused into GEMM X-load) ----
    k_gemm_tc<<<nBlkGemm, BT, SMEM_TC>>>(p_agg, W2, p_h, p_mu, p_inv, p_dinv, 1, N);
    k_zero_stats<<<1, DD>>>(p_colsum, p_sumsq);
    k_aggregate<<<nBlkAgg, BT>>>(p_h, p_rowptr, p_csr, p_dinv, p_agg, nullptr,
                                 p_colsum, p_sumsq, N);
    k_finalize<<<1, DD>>>(p_colsum, p_sumsq, p_mu, p_inv, N);

    // ---- Layer 3 (output = agg + b3, directly into d_out, no stats) ----
    k_gemm_tc<<<nBlkGemm, BT, SMEM_TC>>>(p_agg, W3, p_h, p_mu, p_inv, p_dinv, 1, N);
    k_aggregate<<<nBlkAgg, BT>>>(p_h, p_rowptr, p_csr, p_dinv, out, b3,
                                 nullptr, nullptr, N);
}

// round 6
// speedup vs baseline: 3.3364x; 1.0692x over previous
#include <cuda_runtime.h>
#include <cuda_bf16.h>
#include <cuda_fp16.h>
#include <math.h>

#define DD 128
#define MAXN 100000
#define MAXE 3200000
#define MAXND (MAXN * DD)

// Scratch (static device globals; allocation is forbidden)
__device__ __half g_h[MAXND];      // GEMM output in fp16 (pre-scaled by dinv[row])
__device__ __half g_agg[MAXND];    // aggregation output fp16 (input to next layer)
__device__ int   g_degi[MAXN];
__device__ float g_dinv[MAXN];
__device__ int   g_incl[MAXN];
__device__ int   g_bsum[128];
__device__ int   g_rowptr[MAXN + 1];
__device__ int   g_cursor[MAXN];
__device__ int   g_csr[MAXE];
__device__ float g_colsum[DD];
__device__ float g_sumsq[1];
__device__ float g_mu[DD];
__device__ float g_inv[1];

// ---------------------------------------------------------------------------
__global__ void k_zero_degi(int* deg, int N) {
    int i = blockIdx.x * blockDim.x + threadIdx.x;
    if (i < N) deg[i] = 0;
}

__global__ void k_deg_count(const int* __restrict__ dst, int* deg, int E) {
    int e = blockIdx.x * blockDim.x + threadIdx.x;
    if (e < E) atomicAdd(&deg[dst[e]], 1);
}

__global__ void k_dinv(const int* __restrict__ deg, float* dinv, int N) {
    int i = blockIdx.x * blockDim.x + threadIdx.x;
    if (i < N) dinv[i] = rsqrtf((float)(deg[i] + 1));  // +1 self-loop
}

__global__ void k_scan1(const int* __restrict__ deg, int* incl, int* bsum, int N) {
    __shared__ int sh[1024];
    int i = blockIdx.x * 1024 + threadIdx.x;
    int v = (i < N) ? deg[i] : 0;
    sh[threadIdx.x] = v;
    __syncthreads();
    for (int o = 1; o < 1024; o <<= 1) {
        int t = (threadIdx.x >= o) ? sh[threadIdx.x - o] : 0;
        __syncthreads();
        sh[threadIdx.x] += t;
        __syncthreads();
    }
    if (i < N) incl[i] = sh[threadIdx.x];
    if (threadIdx.x == 1023) bsum[blockIdx.x] = sh[1023];
}

__global__ void k_scan2(int* bsum, int nb) {
    __shared__ int sh[128];
    int t = threadIdx.x;
    int v = (t < nb) ? bsum[t] : 0;
    sh[t] = v;
    __syncthreads();
    for (int o = 1; o < 128; o <<= 1) {
        int u = (t >= o) ? sh[t - o] : 0;
        __syncthreads();
        sh[t] += u;
        __syncthreads();
    }
    if (t < nb) bsum[t] = sh[t] - v;  // exclusive
}

__global__ void k_scan3(const int* __restrict__ deg, const int* __restrict__ incl,
                        const int* __restrict__ bsum, int* rowptr, int* cursor, int N) {
    int i = blockIdx.x * blockDim.x + threadIdx.x;
    if (i < N) {
        int ex = incl[i] - deg[i] + bsum[i >> 10];
        rowptr[i] = ex;
        cursor[i] = ex;
        if (i == N - 1) rowptr[N] = ex + deg[i];
    }
}

__global__ void k_scatter(const int* __restrict__ src, const int* __restrict__ dst,
                          int* cursor, int* csr, int E) {
    int e = blockIdx.x * blockDim.x + threadIdx.x;
    if (e < E) {
        int pos = atomicAdd(&cursor[dst[e]], 1);
        csr[pos] = src[e];
    }
}

// ---------------------------------------------------------------------------
// Tensor-core GEMM: H[N,128] = f(X)[N,128] @ W[128,128] * dinv[row], fp16 out.
// bf16 3-product split (xh*wh + xh*wl + xl*wh) with fp32 accumulation.
#define W_STRIDE 136
#define X_STRIDE 24

__device__ __forceinline__ float cvtf(float v) { return v; }
__device__ __forceinline__ float cvtf(__half v) { return __half2float(v); }

__device__ __forceinline__ void mma16816(float* c, const unsigned* a, const unsigned* b) {
    asm volatile(
        "mma.sync.aligned.m16n8k16.row.col.f32.bf16.bf16.f32 "
        "{%0,%1,%2,%3},{%4,%5,%6,%7},{%8,%9},{%0,%1,%2,%3};"
        : "+f"(c[0]), "+f"(c[1]), "+f"(c[2]), "+f"(c[3])
        : "r"(a[0]), "r"(a[1]), "r"(a[2]), "r"(a[3]), "r"(b[0]), "r"(b[1]));
}

template <typename IT>
__global__ void __launch_bounds__(256, 2)
k_gemm_tc(const IT* __restrict__ X, const float* __restrict__ W,
          __half* __restrict__ H, const float* __restrict__ mu,
          const float* __restrict__ invp, const float* __restrict__ dinv,
          int applyNorm, int N) {
    extern __shared__ __nv_bfloat16 smem[];
    __nv_bfloat16* wh = smem;                       // [128][W_STRIDE]
    __nv_bfloat16* wl = wh + 128 * W_STRIDE;
    __nv_bfloat16* xh = wl + 128 * W_STRIDE;        // [128][X_STRIDE]
    __nv_bfloat16* xl = xh + 128 * X_STRIDE;

    const int tid = threadIdx.x;
    const int warp = tid >> 5;
    const int lane = tid & 31;
    const int g = lane >> 2;
    const int tg = lane & 3;
    const int row0 = blockIdx.x * 128;
    const float inv = applyNorm ? invp[0] : 0.0f;

    // Stage W (hi + lo), transposed to [n][k]
    for (int i = tid; i < DD * DD; i += 256) {
        int k = i >> 7, n = i & 127;
        float w = W[i];
        __nv_bfloat16 hi = __float2bfloat16(w);
        float lo = w - __bfloat162float(hi);
        wh[n * W_STRIDE + k] = hi;
        wl[n * W_STRIDE + k] = __float2bfloat16(lo);
    }

    float c[16][4];
#pragma unroll
    for (int i = 0; i < 16; i++)
#pragma unroll
        for (int j = 0; j < 4; j++) c[i][j] = 0.0f;

    const int arow = warp * 16;

    for (int kc = 0; kc < DD; kc += 16) {
        __syncthreads();
        for (int i = tid; i < 128 * 16; i += 256) {
            int r = i >> 4, kk = i & 15;
            int gr = row0 + r;
            float v = 0.0f;
            if (gr < N) {
                v = cvtf(X[((size_t)gr << 7) + kc + kk]);
                if (applyNorm) v = fmaxf((v - mu[kc + kk]) * inv, 0.0f);
            }
            __nv_bfloat16 hi = __float2bfloat16(v);
            float lo = v - __bfloat162float(hi);
            xh[r * X_STRIDE + kk] = hi;
            xl[r * X_STRIDE + kk] = __float2bfloat16(lo);
        }
        __syncthreads();

        unsigned ah[4], al[4];
        {
            const __nv_bfloat16* ph = xh + (arow + g) * X_STRIDE + 2 * tg;
            const __nv_bfloat16* pl = xl + (arow + g) * X_STRIDE + 2 * tg;
            ah[0] = *(const unsigned*)(ph);
            ah[1] = *(const unsigned*)(ph + 8 * X_STRIDE);
            ah[2] = *(const unsigned*)(ph + 8);
            ah[3] = *(const unsigned*)(ph + 8 * X_STRIDE + 8);
            al[0] = *(const unsigned*)(pl);
            al[1] = *(const unsigned*)(pl + 8 * X_STRIDE);
            al[2] = *(const unsigned*)(pl + 8);
            al[3] = *(const unsigned*)(pl + 8 * X_STRIDE + 8);
        }

#pragma unroll
        for (int nt = 0; nt < 16; nt++) {
            unsigned bh[2], bl[2];
            const __nv_bfloat16* pbh = wh + (nt * 8 + g) * W_STRIDE + kc + 2 * tg;
            const __nv_bfloat16* pbl = wl + (nt * 8 + g) * W_STRIDE + kc + 2 * tg;
            bh[0] = *(const unsigned*)(pbh);
            bh[1] = *(const unsigned*)(pbh + 8);
            bl[0] = *(const unsigned*)(pbl);
            bl[1] = *(const unsigned*)(pbl + 8);
            mma16816(c[nt], ah, bh);
            mma16816(c[nt], ah, bl);
            mma16816(c[nt], al, bh);
        }
    }

    // Epilogue: scale by dinv[row], store half2
    const int r0 = row0 + arow + g;
    const int r1 = r0 + 8;
    const float dv0 = (r0 < N) ? dinv[r0] : 0.0f;
    const float dv1 = (r1 < N) ? dinv[r1] : 0.0f;
#pragma unroll
    for (int nt = 0; nt < 16; nt++) {
        int col = nt * 8 + 2 * tg;
        if (r0 < N)
            *(__half2*)(H + ((size_t)r0 << 7) + col) =
                __floats2half2_rn(c[nt][0] * dv0, c[nt][1] * dv0);
        if (r1 < N)
            *(__half2*)(H + ((size_t)r1 << 7) + col) =
                __floats2half2_rn(c[nt][2] * dv1, c[nt][3] * dv1);
    }
}

// ---------------------------------------------------------------------------
// CSR gather aggregation, 2 rows per warp-load:
// lanes 0-15 cover one neighbor row (16 lanes x uint4 = 256B), lanes 16-31
// cover a second neighbor. Accumulators combined via shfl.xor(16) at the end.
__device__ __forceinline__ void add8(float* a, uint4 u) {
    __half2* p = reinterpret_cast<__half2*>(&u);
#pragma unroll
    for (int i = 0; i < 4; i++) {
        float2 f = __half22float2(p[i]);
        a[2 * i] += f.x;
        a[2 * i + 1] += f.y;
    }
}

template <typename OT, bool HASBIAS, bool STATS>
__global__ void k_aggregate(const __half* __restrict__ h, const int* __restrict__ rowptr,
                            const int* __restrict__ csr, const float* __restrict__ dinv,
                            OT* __restrict__ out, const float* __restrict__ bias,
                            float* colsum, float* sumsq, int N) {
    __shared__ float s_col[DD];
    __shared__ float s_ss;
    if (STATS) {
        if (threadIdx.x < DD) s_col[threadIdx.x] = 0.0f;
        if (threadIdx.x == 0) s_ss = 0.0f;
        __syncthreads();
    }
    const int lane = threadIdx.x & 31;
    const int half = lane >> 4;     // 0 or 1: which neighbor of the pair
    const int cpos = lane & 15;     // 16-lane position within a row (8 cols each)
    const int warp = (blockIdx.x * blockDim.x + threadIdx.x) >> 5;
    const int nwarps = (gridDim.x * blockDim.x) >> 5;
    const uint4* hp = reinterpret_cast<const uint4*>(h);  // row stride 16 uint4

    float cs[8];
    float ssacc = 0.0f;
    if (STATS) {
#pragma unroll
        for (int i = 0; i < 8; i++) cs[i] = 0.0f;
    }

    for (int d = warp; d < N; d += nwarps) {
        float a[8];
#pragma unroll
        for (int i = 0; i < 8; i++) a[i] = 0.0f;

        // self row: half 0 only
        if (half == 0) add8(a, __ldg(&hp[((size_t)d << 4) + cpos]));

        int j = __ldg(&rowptr[d]);
        const int je = __ldg(&rowptr[d + 1]);
        // 8 neighbors per iteration: 4 paired loads
        for (; j + 8 <= je; j += 8) {
            int s0 = __ldg(&csr[j + 0 + half]);
            int s1 = __ldg(&csr[j + 2 + half]);
            int s2 = __ldg(&csr[j + 4 + half]);
            int s3 = __ldg(&csr[j + 6 + half]);
            uint4 u0 = __ldg(&hp[((size_t)s0 << 4) + cpos]);
            uint4 u1 = __ldg(&hp[((size_t)s1 << 4) + cpos]);
            uint4 u2 = __ldg(&hp[((size_t)s2 << 4) + cpos]);
            uint4 u3 = __ldg(&hp[((size_t)s3 << 4) + cpos]);
            add8(a, u0); add8(a, u1); add8(a, u2); add8(a, u3);
        }
        // paired tail
        for (; j + 2 <= je; j += 2) {
            int s = __ldg(&csr[j + half]);
            add8(a, __ldg(&hp[((size_t)s << 4) + cpos]));
        }
        // odd leftover: half 0 only
        if (j < je && half == 0) {
            int s = __ldg(&csr[j]);
            add8(a, __ldg(&hp[((size_t)s << 4) + cpos]));
        }

        // combine the two half-warp streams
#pragma unroll
        for (int i = 0; i < 8; i++)
            a[i] += __shfl_xor_sync(0xffffffffu, a[i], 16);

        const float sc = __ldg(&dinv[d]);
        float o[8];
#pragma unroll
        for (int i = 0; i < 8; i++) o[i] = a[i] * sc;

        if (HASBIAS) {
            // float output path: lane writes 4 floats at col = cpos*8 + half*4
            const float4 b = reinterpret_cast<const float4*>(bias)[cpos * 2 + half];
            float4 v = make_float4(o[half * 4 + 0] + b.x, o[half * 4 + 1] + b.y,
                                   o[half * 4 + 2] + b.z, o[half * 4 + 3] + b.w);
            *reinterpret_cast<float4*>(
                reinterpret_cast<float*>(out) + ((size_t)d << 7) + cpos * 8 + half * 4) = v;
        } else {
            // fp16 output path: lane writes 4 halves at col = cpos*8 + half*4
            __half2 v0 = __floats2half2_rn(o[half * 4 + 0], o[half * 4 + 1]);
            __half2 v1 = __floats2half2_rn(o[half * 4 + 2], o[half * 4 + 3]);
            uint2 pk;
            pk.x = *reinterpret_cast<unsigned*>(&v0);
            pk.y = *reinterpret_cast<unsigned*>(&v1);
            *reinterpret_cast<uint2*>(
                reinterpret_cast<__half*>(out) + ((size_t)d << 7) + cpos * 8 + half * 4) = pk;
        }

        if (STATS && half == 0) {
#pragma unroll
            for (int i = 0; i < 8; i++) {
                cs[i] += o[i];
                ssacc += o[i] * o[i];
            }
        }
    }

    if (STATS) {
        if (half == 0) {
#pragma unroll
            for (int i = 0; i < 8; i++) atomicAdd(&s_col[cpos * 8 + i], cs[i]);
        }
        for (int o = 16; o > 0; o >>= 1) ssacc += __shfl_down_sync(0xffffffff, ssacc, o);
        if (lane == 0) atomicAdd(&s_ss, ssacc);
        __syncthreads();
        if (threadIdx.x < DD) atomicAdd(&colsum[threadIdx.x], s_col[threadIdx.x]);
        if (threadIdx.x == 0) atomicAdd(sumsq, s_ss);
    }
}

// ---------------------------------------------------------------------------
__global__ void k_zero_stats(float* colsum, float* sumsq) {
    int i = threadIdx.x;
    if (i < DD) colsum[i] = 0.0f;
    if (i == 0) sumsq[0] = 0.0f;
}

__global__ void k_finalize(const float* __restrict__ colsum, const float* __restrict__ sumsq,
                           float* mu, float* inv, int N) {
    int c = threadIdx.x;  // 128
    float m = colsum[c] / (float)N;
    mu[c] = m;
    __shared__ float sh[DD];
    sh[c] = m * m;
    __syncthreads();
    for (int o = 64; o > 0; o >>= 1) {
        if (c < o) sh[c] += sh[c + o];
        __syncthreads();
    }
    if (c == 0) {
        float var = sumsq[0] / (float)N - sh[0];
        var = fmaxf(var, 0.0f);
        inv[0] = 1.0f / (sqrtf(var) + 1e-8f);
    }
}

// ---------------------------------------------------------------------------
extern "C" void kernel_launch(void* const* d_in, const int* in_sizes, int n_in,
                              void* d_out, int out_size) {
    const float* x  = (const float*)d_in[0];
    const int* ei   = (const int*)d_in[1];
    const float* W1 = (const float*)d_in[2];
    const float* W2 = (const float*)d_in[4];
    const float* W3 = (const float*)d_in[6];
    const float* b3 = (const float*)d_in[7];
    float* out = (float*)d_out;

    const int N = in_sizes[0] / DD;
    const int E = in_sizes[1] / 2;
    const int* src = ei;
    const int* dst = ei + E;

    float *p_dinv, *p_colsum, *p_sumsq, *p_mu, *p_inv;
    __half *p_h, *p_agg;
    int *p_degi, *p_incl, *p_bsum, *p_rowptr, *p_cursor, *p_csr;
    cudaGetSymbolAddress((void**)&p_h, g_h);
    cudaGetSymbolAddress((void**)&p_agg, g_agg);
    cudaGetSymbolAddress((void**)&p_degi, g_degi);
    cudaGetSymbolAddress((void**)&p_dinv, g_dinv);
    cudaGetSymbolAddress((void**)&p_incl, g_incl);
    cudaGetSymbolAddress((void**)&p_bsum, g_bsum);
    cudaGetSymbolAddress((void**)&p_rowptr, g_rowptr);
    cudaGetSymbolAddress((void**)&p_cursor, g_cursor);
    cudaGetSymbolAddress((void**)&p_csr, g_csr);
    cudaGetSymbolAddress((void**)&p_colsum, g_colsum);
    cudaGetSymbolAddress((void**)&p_sumsq, g_sumsq);
    cudaGetSymbolAddress((void**)&p_mu, g_mu);
    cudaGetSymbolAddress((void**)&p_inv, g_inv);

    const int SMEM_TC = (2 * 128 * W_STRIDE + 2 * 128 * X_STRIDE) * 2; // bytes
    static int attrSet = 0;
    if (!attrSet) {
        cudaFuncSetAttribute(k_gemm_tc<float>, cudaFuncAttributeMaxDynamicSharedMemorySize,
                             SMEM_TC);
        cudaFuncSetAttribute(k_gemm_tc<__half>, cudaFuncAttributeMaxDynamicSharedMemorySize,
                             SMEM_TC);
        attrSet = 1;
    }

    const int BT = 256;
    const int nBlkN = (N + BT - 1) / BT;
    const int nBlkE = (E + BT - 1) / BT;
    const int nBlkGemm = (N + 127) / 128;
    const int nScan = (N + 1023) / 1024;
    const int nBlkAgg = 1480;

    // --- CSR build (by destination) ---
    k_zero_degi<<<nBlkN, BT>>>(p_degi, N);
    k_deg_count<<<nBlkE, BT>>>(dst, p_degi, E);
    k_dinv<<<nBlkN, BT>>>(p_degi, p_dinv, N);
    k_scan1<<<nScan, 1024>>>(p_degi, p_incl, p_bsum, N);
    k_scan2<<<1, 128>>>(p_bsum, nScan);
    k_scan3<<<nBlkN, BT>>>(p_degi, p_incl, p_bsum, p_rowptr, p_cursor, N);
    k_scatter<<<nBlkE, BT>>>(src, dst, p_cursor, p_csr, E);

    // ---- Layer 1 ----
    k_gemm_tc<float><<<nBlkGemm, BT, SMEM_TC>>>(x, W1, p_h, p_mu, p_inv, p_dinv, 0, N);
    k_zero_stats<<<1, DD>>>(p_colsum, p_sumsq);
    k_aggregate<__half, false, true><<<nBlkAgg, BT>>>(
        p_h, p_rowptr, p_csr, p_dinv, p_agg, nullptr, p_colsum, p_sumsq, N);
    k_finalize<<<1, DD>>>(p_colsum, p_sumsq, p_mu, p_inv, N);

    // ---- Layer 2 (PairNorm+ReLU fused into GEMM X-load) ----
    k_gemm_tc<__half><<<nBlkGemm, BT, SMEM_TC>>>(p_agg, W2, p_h, p_mu, p_inv, p_dinv, 1, N);
    k_zero_stats<<<1, DD>>>(p_colsum, p_sumsq);
    k_aggregate<__half, false, true><<<nBlkAgg, BT>>>(
        p_h, p_rowptr, p_csr, p_dinv, p_agg, nullptr, p_colsum, p_sumsq, N);
    k_finalize<<<1, DD>>>(p_colsum, p_sumsq, p_mu, p_inv, N);

    // ---- Layer 3 (output = agg + b3, directly into d_out, fp32) ----
    k_gemm_tc<__half><<<nBlkGemm, BT, SMEM_TC>>>(p_agg, W3, p_h, p_mu, p_inv, p_dinv, 1, N);
    k_aggregate<float, true, false><<<nBlkAgg, BT>>>(
        p_h, p_rowptr, p_csr, p_dinv, out, b3, nullptr, nullptr, N);
}